// round 6
// baseline (speedup 1.0000x reference)
#include <cuda_runtime.h>
#include <math.h>

#define B_ 8
#define N_ 8192
#define D_ 256

// ---------------- device scratch ----------------
__device__ float g_WvT[D_ * D_];
__device__ float g_G[B_ * D_ * D_];
__device__ float g_T[B_ * D_ * D_];
__device__ float g_S[B_ * D_ * D_];
__device__ float g_C[B_ * D_ * D_];
__device__ float g_sk[B_ * D_];
__device__ float g_sv[B_ * D_];
__device__ float g_u[B_ * D_];
__device__ float g_w[B_ * D_];
__device__ float g_r[B_ * D_];
__device__ float g_cnt[B_];
__device__ float g_biasflag;
__device__ unsigned char g_mask8[B_ * N_];
__device__ int g_notint, g_notfloat;

// ---------------- f32x2 helpers ----------------
__device__ __forceinline__ unsigned long long pack2(float x, float y) {
    unsigned long long r;
    asm("mov.b64 %0, {%1, %2};" : "=l"(r) : "f"(x), "f"(y));
    return r;
}
__device__ __forceinline__ void unpack2(unsigned long long v, float &x, float &y) {
    asm("mov.b64 {%0, %1}, %2;" : "=f"(x), "=f"(y) : "l"(v));
}
__device__ __forceinline__ void ffma2(unsigned long long &d, unsigned long long a,
                                      unsigned long long b) {
    asm("fma.rn.f32x2 %0, %1, %2, %0;" : "+l"(d) : "l"(a), "l"(b));
}

// ---------------- cp.async helpers ----------------
__device__ __forceinline__ unsigned smem_u32(const void* p) {
    return (unsigned)__cvta_generic_to_shared(p);
}
__device__ __forceinline__ void cp16(unsigned s, const void* g) {
    asm volatile("cp.async.ca.shared.global [%0], [%1], 16;\n" :: "r"(s), "l"(g));
}
__device__ __forceinline__ void cp_commit() {
    asm volatile("cp.async.commit_group;\n");
}
template <int NW>
__device__ __forceinline__ void cp_wait() {
    asm volatile("cp.async.wait_group %0;\n" :: "n"(NW));
}

// ---------------- mask canonicalization ----------------
__global__ void k_maskdetect(const void* mp) {
    int i = blockIdx.x * blockDim.x + threadIdx.x;   // [0, 16384)
    int v = ((const int*)mp)[i];
    if (v != 0 && v != 1) atomicOr(&g_notint, 1);
    float f = ((const float*)mp)[i];
    if (!(f == 0.0f || f == 1.0f)) atomicOr(&g_notfloat, 1);
}
__global__ void k_maskconv(const void* mp) {
    int i = blockIdx.x * blockDim.x + threadIdx.x;   // [0, B*N)
    unsigned char m;
    if (!g_notint)        m = (((const int*)mp)[i] != 0);
    else if (!g_notfloat) m = (((const float*)mp)[i] != 0.0f);
    else                  m = (((const unsigned char*)mp)[i] != 0);
    g_mask8[i] = m;
}

// ---------------- G-gram: G[b] += sum_n mask*key_n value_n^T ----------------
// 128x128 tile, 256 threads (TM=TN=8), KSTEP=16, 2-stage cp.async pipeline.
#define GKS 16
#define GNCHUNK 8
__global__ void __launch_bounds__(256, 2) gemm_gram(
    const float* __restrict__ key, const float* __restrict__ val)
{
    const int t  = threadIdx.x;
    const int tx = t & 15;
    const int ty = t >> 4;
    const int b  = blockIdx.z >> 3;
    const int ch = blockIdx.z & 7;
    const int m0 = blockIdx.y * 128;
    const int n0 = blockIdx.x * 128;
    const int kbeg = ch * (N_ / GNCHUNK);
    const int kLen = N_ / GNCHUNK;

    const float* A  = key + (long)b * N_ * D_;
    const float* Bv = val + (long)b * N_ * D_;
    const unsigned char* mp = g_mask8 + (long)b * N_;
    float* C = g_G + (long)b * D_ * D_;

    __shared__ __align__(16) float sA[2][GKS * 128];
    __shared__ __align__(16) float sB[2][GKS * 128];

    // each thread owns 2 float4 slots per tile: idx = t, t+256 ; kk=idx/32, mq=idx%32
    int akk[2], amq[2];
#pragma unroll
    for (int r = 0; r < 2; r++) { int idx = t + r * 256; akk[r] = idx >> 5; amq[r] = idx & 31; }

    unsigned long long acc[8][4];
#pragma unroll
    for (int i = 0; i < 8; i++)
#pragma unroll
        for (int j = 0; j < 4; j++) acc[i][j] = 0ull;

    const int NIT = kLen / GKS;

    // prologue: stage 0
    {
        int k0 = kbeg;
#pragma unroll
        for (int r = 0; r < 2; r++) {
            cp16(smem_u32(&sA[0][akk[r] * 128 + amq[r] * 4]),
                 A + (long)(k0 + akk[r]) * D_ + m0 + amq[r] * 4);
            cp16(smem_u32(&sB[0][akk[r] * 128 + amq[r] * 4]),
                 Bv + (long)(k0 + akk[r]) * D_ + n0 + amq[r] * 4);
        }
        cp_commit();
    }

    for (int it = 0; it < NIT; it++) {
        int buf = it & 1;
        if (it + 1 < NIT) {
            int k0 = kbeg + (it + 1) * GKS;
#pragma unroll
            for (int r = 0; r < 2; r++) {
                cp16(smem_u32(&sA[buf ^ 1][akk[r] * 128 + amq[r] * 4]),
                     A + (long)(k0 + akk[r]) * D_ + m0 + amq[r] * 4);
                cp16(smem_u32(&sB[buf ^ 1][akk[r] * 128 + amq[r] * 4]),
                     Bv + (long)(k0 + akk[r]) * D_ + n0 + amq[r] * 4);
            }
            cp_commit();
            cp_wait<1>();
        } else {
            cp_wait<0>();
        }

        // zero my masked A slots (my own cp.asyncs have landed)
        {
            int k0 = kbeg + it * GKS;
#pragma unroll
            for (int r = 0; r < 2; r++) {
                if (mp[k0 + akk[r]]) {
                    float4 z = make_float4(0.f, 0.f, 0.f, 0.f);
                    *(float4*)&sA[buf][akk[r] * 128 + amq[r] * 4] = z;
                }
            }
        }
        __syncthreads();

#pragma unroll
        for (int kk = 0; kk < GKS; kk++) {
            unsigned long long bb[4];
            const unsigned long long* bp =
                reinterpret_cast<const unsigned long long*>(&sB[buf][kk * 128 + tx * 8]);
#pragma unroll
            for (int j = 0; j < 4; j++) bb[j] = bp[j];

            float av[8];
            float4 a0 = *(const float4*)&sA[buf][kk * 128 + ty * 8];
            float4 a1 = *(const float4*)&sA[buf][kk * 128 + ty * 8 + 4];
            av[0] = a0.x; av[1] = a0.y; av[2] = a0.z; av[3] = a0.w;
            av[4] = a1.x; av[5] = a1.y; av[6] = a1.z; av[7] = a1.w;
#pragma unroll
            for (int i = 0; i < 8; i++) {
                unsigned long long aa = pack2(av[i], av[i]);
#pragma unroll
                for (int j = 0; j < 4; j++) ffma2(acc[i][j], aa, bb[j]);
            }
        }
        __syncthreads();
    }

    // epilogue: atomic accumulate
#pragma unroll
    for (int i = 0; i < 8; i++) {
        int m = m0 + ty * 8 + i;
        float vals[8];
#pragma unroll
        for (int j = 0; j < 4; j++) unpack2(acc[i][j], vals[2 * j], vals[2 * j + 1]);
        float* crow = C + (long)m * D_ + n0 + tx * 8;
#pragma unroll
        for (int j = 0; j < 8; j++) atomicAdd(&crow[j], vals[j]);
    }
}

// ---------------- out = query @ C + r ----------------
// 128x128 tile, 256 threads, KSTEP=16, 2-stage cp.async; A m-major (padded smem).
#define OKS 16
#define OPAD 20   // row stride in floats (16B-aligned: 80 bytes)
__global__ void __launch_bounds__(256, 2) gemm_out(
    const float* __restrict__ query, float* __restrict__ outp)
{
    const int t  = threadIdx.x;
    const int tx = t & 15;
    const int ty = t >> 4;
    const int b  = blockIdx.z;
    const int m0 = blockIdx.y * 128;
    const int n0 = blockIdx.x * 128;

    const float* A  = query + (long)b * N_ * D_;
    const float* Bc = g_C + (long)b * D_ * D_;
    float* C = outp + (long)b * N_ * D_;

    __shared__ __align__(16) float sA[2][128 * OPAD];
    __shared__ __align__(16) float sB[2][OKS * 128];

    // A: 512 float4/stage: idx -> mr = idx/4, kq = idx%4
    // B: 512 float4/stage: idx -> kk = idx/32, nq = idx%32
    int amr[2], akq[2], bkk[2], bnq[2];
#pragma unroll
    for (int r = 0; r < 2; r++) {
        int idx = t + r * 256;
        amr[r] = idx >> 2;  akq[r] = idx & 3;
        bkk[r] = idx >> 5;  bnq[r] = idx & 31;
    }

    unsigned long long acc[8][4];
#pragma unroll
    for (int i = 0; i < 8; i++)
#pragma unroll
        for (int j = 0; j < 4; j++) acc[i][j] = 0ull;

    const int NIT = D_ / OKS;   // 16

    {
#pragma unroll
        for (int r = 0; r < 2; r++) {
            cp16(smem_u32(&sA[0][amr[r] * OPAD + akq[r] * 4]),
                 A + (long)(m0 + amr[r]) * D_ + akq[r] * 4);
            cp16(smem_u32(&sB[0][bkk[r] * 128 + bnq[r] * 4]),
                 Bc + (long)bkk[r] * D_ + n0 + bnq[r] * 4);
        }
        cp_commit();
    }

    for (int it = 0; it < NIT; it++) {
        int buf = it & 1;
        if (it + 1 < NIT) {
            int k0 = (it + 1) * OKS;
#pragma unroll
            for (int r = 0; r < 2; r++) {
                cp16(smem_u32(&sA[buf ^ 1][amr[r] * OPAD + akq[r] * 4]),
                     A + (long)(m0 + amr[r]) * D_ + k0 + akq[r] * 4);
                cp16(smem_u32(&sB[buf ^ 1][bkk[r] * 128 + bnq[r] * 4]),
                     Bc + (long)(k0 + bkk[r]) * D_ + n0 + bnq[r] * 4);
            }
            cp_commit();
            cp_wait<1>();
        } else {
            cp_wait<0>();
        }
        __syncthreads();

#pragma unroll
        for (int kk = 0; kk < OKS; kk++) {
            unsigned long long bb[4];
            const unsigned long long* bp =
                reinterpret_cast<const unsigned long long*>(&sB[buf][kk * 128 + tx * 8]);
#pragma unroll
            for (int j = 0; j < 4; j++) bb[j] = bp[j];

            float av[8];
#pragma unroll
            for (int i = 0; i < 8; i++) av[i] = sA[buf][(ty * 8 + i) * OPAD + kk];
#pragma unroll
            for (int i = 0; i < 8; i++) {
                unsigned long long aa = pack2(av[i], av[i]);
#pragma unroll
                for (int j = 0; j < 4; j++) ffma2(acc[i][j], aa, bb[j]);
            }
        }
        __syncthreads();
    }

#pragma unroll
    for (int i = 0; i < 8; i++) {
        int m = m0 + ty * 8 + i;
        float vals[8];
#pragma unroll
        for (int j = 0; j < 4; j++) unpack2(acc[i][j], vals[2 * j], vals[2 * j + 1]);
        float* crow = C + (long)m * D_ + n0 + tx * 8;
#pragma unroll
        for (int q = 0; q < 2; q++) {
            int col = n0 + tx * 8 + q * 4;
            float4 o;
            o.x = vals[q * 4 + 0] + g_r[b * D_ + col + 0];
            o.y = vals[q * 4 + 1] + g_r[b * D_ + col + 1];
            o.z = vals[q * 4 + 2] + g_r[b * D_ + col + 2];
            o.w = vals[q * 4 + 3] + g_r[b * D_ + col + 3];
            *(float4*)(&crow[q * 4]) = o;
        }
    }
}

// ---------------- small GEMM template (256x256 matrices) ----------------
// C[m][n] = sum_k A(k,m)*B(k,n); AKM: A K-major; EPI: 0=store, 2=bias-rank1+scale
template <int BM, int BN, int TM, int TN, int KSTEP, bool AKM, int EPI>
__global__ void __launch_bounds__((BM / TM) * (BN / TN)) gemm_tpl(
    const float* __restrict__ Ag, const float* __restrict__ Bg, float* __restrict__ Cg,
    long sAb, long sBb, long sCb,
    const float* __restrict__ bkv, const float* __restrict__ bvv, float scale)
{
    constexpr int TX = BN / TN;
    constexpr int TY = BM / TM;
    constexpr int NT = TX * TY;

    const int t  = threadIdx.x;
    const int tx = t % TX;
    const int ty = t / TX;
    const int b  = blockIdx.z;

    const float* A  = Ag + (long)b * sAb;
    const float* Bm = Bg + (long)b * sBb;
    float*       C  = Cg + (long)b * sCb;

    const int m0 = blockIdx.y * BM;
    const int n0 = blockIdx.x * BN;

    __shared__ float sA[AKM ? (KSTEP * BM) : (BM * (KSTEP + 1))];
    __shared__ float sB[KSTEP * BN];

    unsigned long long acc[TM][TN / 2];
#pragma unroll
    for (int i = 0; i < TM; i++)
#pragma unroll
        for (int j = 0; j < TN / 2; j++) acc[i][j] = 0ull;

    for (int k0 = 0; k0 < D_; k0 += KSTEP) {
        if constexpr (AKM) {
            constexpr int AF4 = KSTEP * BM / 4;
#pragma unroll
            for (int r = 0; r < AF4 / NT; r++) {
                int i  = t + r * NT;
                int kk = i / (BM / 4);
                int mq = i % (BM / 4);
                float4 v = *(const float4*)(A + (long)(k0 + kk) * D_ + m0 + mq * 4);
                *(float4*)(&sA[kk * BM + mq * 4]) = v;
            }
        } else {
            constexpr int AF4 = BM * (KSTEP / 4);
#pragma unroll
            for (int r = 0; r < AF4 / NT; r++) {
                int i  = t + r * NT;
                int mr = i / (KSTEP / 4);
                int kq = i % (KSTEP / 4);
                float4 v = *(const float4*)(A + (long)(m0 + mr) * D_ + k0 + kq * 4);
                int base = mr * (KSTEP + 1) + kq * 4;
                sA[base + 0] = v.x; sA[base + 1] = v.y;
                sA[base + 2] = v.z; sA[base + 3] = v.w;
            }
        }
        {
            constexpr int BF4 = KSTEP * BN / 4;
#pragma unroll
            for (int r = 0; r < BF4 / NT; r++) {
                int i  = t + r * NT;
                int kk = i / (BN / 4);
                int nq = i % (BN / 4);
                float4 v = *(const float4*)(Bm + (long)(k0 + kk) * D_ + n0 + nq * 4);
                *(float4*)(&sB[kk * BN + nq * 4]) = v;
            }
        }
        __syncthreads();

#pragma unroll 4
        for (int kk = 0; kk < KSTEP; kk++) {
            unsigned long long bb[TN / 2];
            const unsigned long long* bp =
                reinterpret_cast<const unsigned long long*>(&sB[kk * BN + tx * TN]);
#pragma unroll
            for (int j = 0; j < TN / 2; j++) bb[j] = bp[j];

            float av[TM];
            if constexpr (AKM) {
#pragma unroll
                for (int q = 0; q < TM / 4; q++) {
                    float4 va = *(const float4*)(&sA[kk * BM + ty * TM + q * 4]);
                    av[q * 4 + 0] = va.x; av[q * 4 + 1] = va.y;
                    av[q * 4 + 2] = va.z; av[q * 4 + 3] = va.w;
                }
            } else {
#pragma unroll
                for (int i = 0; i < TM; i++)
                    av[i] = sA[(ty * TM + i) * (KSTEP + 1) + kk];
            }
#pragma unroll
            for (int i = 0; i < TM; i++) {
                unsigned long long aa = pack2(av[i], av[i]);
#pragma unroll
                for (int j = 0; j < TN / 2; j++) ffma2(acc[i][j], aa, bb[j]);
            }
        }
        __syncthreads();
    }

#pragma unroll
    for (int i = 0; i < TM; i++) {
        int m = m0 + ty * TM + i;
        float vals[TN];
#pragma unroll
        for (int j = 0; j < TN / 2; j++) unpack2(acc[i][j], vals[2 * j], vals[2 * j + 1]);
        float* crow = C + (long)m * D_ + n0 + tx * TN;

        if constexpr (EPI == 2) {
            float um  = g_u[b * D_ + m];
            float bkm = bkv[m];
            float cb  = g_cnt[b];
#pragma unroll
            for (int j = 0; j < TN; j++) {
                int col = n0 + tx * TN + j;
                crow[j] = scale * (vals[j] + um * bvv[col] + bkm * g_w[b * D_ + col]
                                   + cb * bkm * bvv[col]);
            }
        } else {
#pragma unroll
            for (int q = 0; q < TN / 4; q++) {
                float4 o;
                o.x = vals[q * 4 + 0]; o.y = vals[q * 4 + 1];
                o.z = vals[q * 4 + 2]; o.w = vals[q * 4 + 3];
                *(float4*)(&crow[q * 4]) = o;
            }
        }
    }
}

// ---------------- small kernels ----------------
__global__ void k_zero() {
    int i = blockIdx.x * blockDim.x + threadIdx.x;
    if (i < B_ * D_ * D_) g_G[i] = 0.0f;
    if (i < B_ * D_) { g_sk[i] = 0.0f; g_sv[i] = 0.0f; }
    if (i < B_) g_cnt[i] = 0.0f;
    if (i == 0) { g_notint = 0; g_notfloat = 0; }
}

__global__ void k_flag(const float* __restrict__ bk, const float* __restrict__ bv) {
    __shared__ float red[D_];
    int t = threadIdx.x;
    red[t] = fabsf(bk[t]) + fabsf(bv[t]);
    __syncthreads();
    for (int s = 128; s > 0; s >>= 1) {
        if (t < s) red[t] += red[t + s];
        __syncthreads();
    }
    if (t == 0) g_biasflag = red[0];
}

__global__ void k_tr(const float* __restrict__ Wv) {
    g_WvT[blockIdx.x * D_ + threadIdx.x] = Wv[threadIdx.x * D_ + blockIdx.x];
}

__global__ void k_sums(const float* __restrict__ key, const float* __restrict__ val) {
    if (g_biasflag == 0.0f) return;
    int b = blockIdx.x;
    int d = threadIdx.x;
    float sk = 0.0f, sv = 0.0f, c = 0.0f;
    for (int n = 0; n < N_; n++) {
        float ml = g_mask8[(long)b * N_ + n] ? 0.0f : 1.0f;
        sk += ml * key[((long)b * N_ + n) * D_ + d];
        sv += ml * val[((long)b * N_ + n) * D_ + d];
        c  += ml;
    }
    g_sk[b * D_ + d] = sk;
    g_sv[b * D_ + d] = sv;
    if (d == 0) g_cnt[b] = c;
}

__global__ void k_uw(const float* __restrict__ Wk, const float* __restrict__ Wv) {
    int b = blockIdx.x;
    int d = threadIdx.x;
    float u = 0.0f, w = 0.0f;
    for (int j = 0; j < D_; j++) {
        u += Wk[d * D_ + j] * g_sk[b * D_ + j];
        w += g_sv[b * D_ + j] * Wv[d * D_ + j];
    }
    g_u[b * D_ + d] = u;
    g_w[b * D_ + d] = w;
}

__global__ void k_softmax() {
    int b = blockIdx.x;
    int e = threadIdx.x;
    float* p = g_S + (long)b * D_ * D_ + e;
    float mx = -1e30f;
    for (int d = 0; d < D_; d++) mx = fmaxf(mx, p[d * D_]);
    float s = 0.0f;
    for (int d = 0; d < D_; d++) {
        float v = expf(p[d * D_] - mx);
        s += v;
        p[d * D_] = v;
    }
    float inv = 1.0f / s;
    for (int d = 0; d < D_; d++) p[d * D_] *= inv;
}

__global__ void k_r(const float* __restrict__ bq) {
    int b = blockIdx.x;
    int e = threadIdx.x;
    float r = 0.0f;
    for (int d = 0; d < D_; d++) r += bq[d] * g_S[(long)b * D_ * D_ + d * D_ + e];
    g_r[b * D_ + e] = r;
}

// ---------------- launch ----------------
extern "C" void kernel_launch(void* const* d_in, const int* in_sizes, int n_in,
                              void* d_out, int out_size)
{
    const float* query = (const float*)d_in[0];
    const float* key   = (const float*)d_in[1];
    const float* value = (const float*)d_in[2];
    const void*  maskp = d_in[3];

    int wbase = 4;
    if (wbase < n_in && in_sizes[wbase] < 32) wbase++;   // skip need_weights scalar

    const float* Wq = (const float*)d_in[wbase + 0];
    const float* bq = (const float*)d_in[wbase + 1];
    const float* Wk = (const float*)d_in[wbase + 2];
    const float* bk = (const float*)d_in[wbase + 3];
    const float* Wv = (const float*)d_in[wbase + 4];
    const float* bv = (const float*)d_in[wbase + 5];
    float* out = (float*)d_out;

    float *pG, *pT, *pS, *pC, *pWvT;
    cudaGetSymbolAddress((void**)&pG, g_G);
    cudaGetSymbolAddress((void**)&pT, g_T);
    cudaGetSymbolAddress((void**)&pS, g_S);
    cudaGetSymbolAddress((void**)&pC, g_C);
    cudaGetSymbolAddress((void**)&pWvT, g_WvT);

    const float scale = 0.3535533905932738f;  // 1/sqrt(B)

    // launches 1-5 (trivial) so that launch 6 = gemm_gram for ncu -s 5 -c 1
    k_zero<<<(B_ * D_ * D_ + 255) / 256, 256>>>();                 // 1
    k_maskdetect<<<16384 / 256, 256>>>(maskp);                     // 2
    k_maskconv<<<(B_ * N_) / 256, 256>>>(maskp);                   // 3
    k_flag<<<1, D_>>>(bk, bv);                                     // 4
    k_tr<<<D_, D_>>>(Wv);                                          // 5

    // 6: G[b] = sum_n mask * key_n value_n^T  (8 chunks, atomic accum)
    gemm_gram<<<dim3(2, 2, B_ * GNCHUNK), 256>>>(key, value);

    // bias path (early-exit when biases are zero)
    k_sums<<<B_, D_>>>(key, value);
    k_uw<<<B_, D_>>>(Wk, Wv);

    // T = Wk @ G
    gemm_tpl<64, 64, 4, 4, 32, false, 0>
        <<<dim3(4, 4, B_), 256>>>(Wk, pG, pT, 0L, (long)D_ * D_, (long)D_ * D_,
                                  nullptr, nullptr, 0.0f);
    // S = scale * (T @ WvT + bias terms)
    gemm_tpl<64, 64, 4, 4, 32, false, 2>
        <<<dim3(4, 4, B_), 256>>>(pT, pWvT, pS, (long)D_ * D_, 0L, (long)D_ * D_,
                                  bk, bv, scale);

    k_softmax<<<B_, D_>>>();
    k_r<<<B_, D_>>>(bq);

    // C = Wq^T @ aw
    gemm_tpl<64, 64, 4, 4, 32, true, 0>
        <<<dim3(4, 4, B_), 256>>>(Wq, pS, pC, 0L, (long)D_ * D_, (long)D_ * D_,
                                  nullptr, nullptr, 0.0f);

    // out = query @ C + r
    gemm_out<<<dim3(2, 64, B_), 256>>>(query, out);
}

// round 9
// speedup vs baseline: 2.3657x; 2.3657x over previous
#include <cuda_runtime.h>
#include <cuda_fp16.h>
#include <math.h>
#include <cstdint>

#define B_ 8
#define N_ 8192
#define D_ 256

// ---------------- device scratch ----------------
__device__ float g_WvT[D_ * D_];
__device__ float g_G[B_ * D_ * D_];
__device__ float g_T[B_ * D_ * D_];
__device__ float g_S[B_ * D_ * D_];
__device__ float g_C[B_ * D_ * D_];          // C[d][e]
__device__ float g_sk[B_ * D_];
__device__ float g_sv[B_ * D_];
__device__ float g_u[B_ * D_];
__device__ float g_w[B_ * D_];
__device__ float g_r[B_ * D_];
__device__ float g_cnt[B_];
__device__ float g_biasflag;
__device__ unsigned char g_mask8[B_ * N_];
__device__ int g_notint, g_notfloat;
__device__ __half g_CTh[B_ * D_ * D_];       // C split hi [d][e]
__device__ __half g_CTl[B_ * D_ * D_];       // C split lo

// ---------------- f32x2 (small SIMT GEMMs) ----------------
__device__ __forceinline__ unsigned long long pack2(float x, float y) {
    unsigned long long r;
    asm("mov.b64 %0, {%1, %2};" : "=l"(r) : "f"(x), "f"(y));
    return r;
}
__device__ __forceinline__ void unpack2(unsigned long long v, float &x, float &y) {
    asm("mov.b64 {%0, %1}, %2;" : "=f"(x), "=f"(y) : "l"(v));
}
__device__ __forceinline__ void ffma2(unsigned long long &d, unsigned long long a,
                                      unsigned long long b) {
    asm("fma.rn.f32x2 %0, %1, %2, %0;" : "+l"(d) : "l"(a), "l"(b));
}

// ---------------- cp.async ----------------
__device__ __forceinline__ void cp16(uint32_t s, const void* g) {
    asm volatile("cp.async.ca.shared.global [%0], [%1], 16;\n" :: "r"(s), "l"(g));
}
__device__ __forceinline__ void cp_commit() { asm volatile("cp.async.commit_group;\n"); }
template <int NW>
__device__ __forceinline__ void cp_wait() {
    asm volatile("cp.async.wait_group %0;\n" :: "n"(NW));
}

// ---------------- mma.sync helpers ----------------
__device__ __forceinline__ void ldsm4t(uint32_t addr, uint32_t &r0, uint32_t &r1,
                                       uint32_t &r2, uint32_t &r3) {
    asm volatile("ldmatrix.sync.aligned.m8n8.x4.trans.shared.b16 {%0,%1,%2,%3}, [%4];"
                 : "=r"(r0), "=r"(r1), "=r"(r2), "=r"(r3) : "r"(addr));
}
__device__ __forceinline__ void mma16816(float* c, uint32_t a0, uint32_t a1,
                                         uint32_t a2, uint32_t a3,
                                         uint32_t b0, uint32_t b1) {
    asm volatile(
        "mma.sync.aligned.m16n8k16.row.col.f32.f16.f16.f32 "
        "{%0,%1,%2,%3}, {%4,%5,%6,%7}, {%8,%9}, {%0,%1,%2,%3};"
        : "+f"(c[0]), "+f"(c[1]), "+f"(c[2]), "+f"(c[3])
        : "r"(a0), "r"(a1), "r"(a2), "r"(a3), "r"(b0), "r"(b1));
}

// unified .trans fragment address: tile stored [k][136] halfs, k-major
__device__ __forceinline__ uint32_t frag_addr(uint32_t tile_base, int lane, int coff) {
    int lrow = (lane & 7) + ((lane & 16) >> 1);
    int lcol = coff + (lane & 8);
    return tile_base + (uint32_t)(lrow * 136 + lcol) * 2;
}

// ---------------- mask canonicalization ----------------
__global__ void k_maskdetect(const void* mp) {
    int i = blockIdx.x * blockDim.x + threadIdx.x;   // [0, 16384)
    int v = ((const int*)mp)[i];
    if (v != 0 && v != 1) atomicOr(&g_notint, 1);
    float f = ((const float*)mp)[i];
    if (!(f == 0.0f || f == 1.0f)) atomicOr(&g_notfloat, 1);
}
__global__ void k_maskconv(const void* mp) {
    int i = blockIdx.x * blockDim.x + threadIdx.x;   // [0, B*N)
    unsigned char m;
    if (!g_notint)        m = (((const int*)mp)[i] != 0);
    else if (!g_notfloat) m = (((const float*)mp)[i] != 0.0f);
    else                  m = (((const unsigned char*)mp)[i] != 0);
    g_mask8[i] = m;
}

// ================= G = K^T V (masked) via HMMA, fp16 split =================
// CTA: 128(j) x 128(l) tile, 256 thr / 8 warps (warp 64x32), k-chunked 16-way.
#define GCH 16
#define G_STA 0                      // fp32 staging A: 3 x 8192
#define G_STB 24576                  // fp32 staging B: 3 x 8192
#define G_FAH 49152                  // fp16 A hi: 2 x 4352
#define G_FAL 57856
#define G_FBH 66560
#define G_FBL 75264
#define G_SMEM 83968

__global__ void __launch_bounds__(256) gemm_gram_mma(
    const float* __restrict__ key, const float* __restrict__ val)
{
    extern __shared__ __align__(16) char sm[];
    const uint32_t sb = (uint32_t)__cvta_generic_to_shared(sm);
    const int t = threadIdx.x, lane = t & 31, w = t >> 5;
    const int wj = w & 1, wl = w >> 1;
    const int n0 = blockIdx.x * 128, m0 = blockIdx.y * 128;
    const int b = blockIdx.z >> 4, ch = blockIdx.z & 15;
    const int kbeg = ch * (N_ / GCH);
    const int NIT = (N_ / GCH) / 16;    // 32

    const float* Ak = key + (long)b * N_ * D_;
    const float* Bv = val + (long)b * N_ * D_;
    const unsigned char* mrow = g_mask8 + (long)b * N_ + kbeg;

    float acc[4][4][4];
#pragma unroll
    for (int i = 0; i < 4; i++)
#pragma unroll
        for (int j = 0; j < 4; j++)
#pragma unroll
            for (int q = 0; q < 4; q++) acc[i][j][q] = 0.0f;

    // prologue: 3 stages
#pragma unroll
    for (int j = 0; j < 3; j++) {
        int k0 = kbeg + j * 16, slot = j % 3;
#pragma unroll
        for (int r = 0; r < 2; r++) {
            int idx = t + r * 256, kr = idx >> 5, c = idx & 31;
            cp16(sb + G_STA + slot * 8192 + (kr * 128 + c * 4) * 4,
                 Ak + (long)(k0 + kr) * D_ + m0 + c * 4);
            cp16(sb + G_STB + slot * 8192 + (kr * 128 + c * 4) * 4,
                 Bv + (long)(k0 + kr) * D_ + n0 + c * 4);
        }
        cp_commit();
    }

    for (int it = 0; it < NIT; it++) {
        const int slot = it % 3, fs = it & 1;
        cp_wait<2>();
        __syncthreads();
        // convert staging -> fp16 hi/lo tiles [16][136]
#pragma unroll
        for (int p = 0; p < 4; p++) {
            int k = (t >> 6) + p * 4, m2 = (t & 63) * 2;
            // A (key) with mask
            float2 va = *(const float2*)(sm + G_STA + slot * 8192 + (k * 128 + m2) * 4);
            if (mrow[it * 16 + k]) { va.x = 0.0f; va.y = 0.0f; }
            __half2 ha = __floats2half2_rn(va.x, va.y);
            float2 hb = __half22float2(ha);
            __half2 la = __floats2half2_rn(va.x - hb.x, va.y - hb.y);
            *(__half2*)(sm + G_FAH + fs * 4352 + (k * 136 + m2) * 2) = ha;
            *(__half2*)(sm + G_FAL + fs * 4352 + (k * 136 + m2) * 2) = la;
            // B (value)
            float2 vb = *(const float2*)(sm + G_STB + slot * 8192 + (k * 128 + m2) * 4);
            __half2 hB = __floats2half2_rn(vb.x, vb.y);
            float2 hbb = __half22float2(hB);
            __half2 lB = __floats2half2_rn(vb.x - hbb.x, vb.y - hbb.y);
            *(__half2*)(sm + G_FBH + fs * 4352 + (k * 136 + m2) * 2) = hB;
            *(__half2*)(sm + G_FBL + fs * 4352 + (k * 136 + m2) * 2) = lB;
        }
        __syncthreads();
        // issue stage it+3
        if (it + 3 < NIT) {
            int k0 = kbeg + (it + 3) * 16, s2 = (it + 3) % 3;
#pragma unroll
            for (int r = 0; r < 2; r++) {
                int idx = t + r * 256, kr = idx >> 5, c = idx & 31;
                cp16(sb + G_STA + s2 * 8192 + (kr * 128 + c * 4) * 4,
                     Ak + (long)(k0 + kr) * D_ + m0 + c * 4);
                cp16(sb + G_STB + s2 * 8192 + (kr * 128 + c * 4) * 4,
                     Bv + (long)(k0 + kr) * D_ + n0 + c * 4);
            }
        }
        cp_commit();

        // fragments
        uint32_t aH[4][4], aL[4][4], bH[4][2], bL[4][2];
#pragma unroll
        for (int mt = 0; mt < 4; mt++) {
            int coff = wj * 64 + mt * 16;
            ldsm4t(frag_addr(sb + G_FAH + fs * 4352, lane, coff),
                   aH[mt][0], aH[mt][1], aH[mt][2], aH[mt][3]);
            ldsm4t(frag_addr(sb + G_FAL + fs * 4352, lane, coff),
                   aL[mt][0], aL[mt][1], aL[mt][2], aL[mt][3]);
        }
#pragma unroll
        for (int p = 0; p < 2; p++) {
            int coff = wl * 32 + p * 16;
            uint32_t r0, r1, r2, r3;
            ldsm4t(frag_addr(sb + G_FBH + fs * 4352, lane, coff), r0, r1, r2, r3);
            bH[2 * p][0] = r0; bH[2 * p][1] = r2;
            bH[2 * p + 1][0] = r1; bH[2 * p + 1][1] = r3;
            ldsm4t(frag_addr(sb + G_FBL + fs * 4352, lane, coff), r0, r1, r2, r3);
            bL[2 * p][0] = r0; bL[2 * p][1] = r2;
            bL[2 * p + 1][0] = r1; bL[2 * p + 1][1] = r3;
        }
#pragma unroll
        for (int mt = 0; mt < 4; mt++)
#pragma unroll
            for (int nt = 0; nt < 4; nt++) {
                mma16816(acc[mt][nt], aH[mt][0], aH[mt][1], aH[mt][2], aH[mt][3],
                         bH[nt][0], bH[nt][1]);
                mma16816(acc[mt][nt], aH[mt][0], aH[mt][1], aH[mt][2], aH[mt][3],
                         bL[nt][0], bL[nt][1]);
                mma16816(acc[mt][nt], aL[mt][0], aL[mt][1], aL[mt][2], aL[mt][3],
                         bH[nt][0], bH[nt][1]);
            }
    }

    // epilogue: atomic accumulate into g_G
    const int g = lane >> 2, tig = lane & 3;
    float* Cb = g_G + (long)b * D_ * D_;
#pragma unroll
    for (int mt = 0; mt < 4; mt++)
#pragma unroll
        for (int nt = 0; nt < 4; nt++) {
            int row = m0 + wj * 64 + mt * 16 + g;
            int col = n0 + wl * 32 + nt * 8 + 2 * tig;
            float* cr = Cb + (long)row * D_ + col;
            atomicAdd(cr,             acc[mt][nt][0]);
            atomicAdd(cr + 1,         acc[mt][nt][1]);
            atomicAdd(cr + 8 * D_,     acc[mt][nt][2]);
            atomicAdd(cr + 8 * D_ + 1, acc[mt][nt][3]);
        }
}

// ================= out = query @ C + r via HMMA, fp16 split =================
#define O_STA 0                      // fp32 staging A: 3 x 8192
#define O_FAH 24576                  // fp16 A hi: 2 x 4352
#define O_FAL 33280
#define O_FBH 41984                  // fp16 B hi: 4 x 4352
#define O_FBL 59392
#define O_SMEM 76800

__global__ void __launch_bounds__(256) gemm_out_mma(
    const float* __restrict__ query, float* __restrict__ outp)
{
    extern __shared__ __align__(16) char sm[];
    const uint32_t sb = (uint32_t)__cvta_generic_to_shared(sm);
    const int t = threadIdx.x, lane = t & 31, w = t >> 5;
    const int wj = w & 1, wl = w >> 1;
    const int n0 = blockIdx.x * 128, m0 = blockIdx.y * 128;
    const int b = blockIdx.z;
    const int NIT = D_ / 16;   // 16

    const float* Aq = query + ((long)b * N_ + m0) * D_;
    const __half* Bh = g_CTh + (long)b * D_ * D_;
    const __half* Bl = g_CTl + (long)b * D_ * D_;

    float acc[4][4][4];
#pragma unroll
    for (int i = 0; i < 4; i++)
#pragma unroll
        for (int j = 0; j < 4; j++)
#pragma unroll
            for (int q = 0; q < 4; q++) acc[i][j][q] = 0.0f;

#pragma unroll
    for (int j = 0; j < 3; j++) {
        int k0 = j * 16, as = j % 3, bs = j % 4;
#pragma unroll
        for (int r = 0; r < 2; r++) {
            int idx = t + r * 256, m = idx >> 2, c = idx & 3;
            cp16(sb + O_STA + as * 8192 + (m * 16 + c * 4) * 4,
                 Aq + (long)m * D_ + k0 + c * 4);
        }
        { int kr = t >> 4, c = t & 15;
          cp16(sb + O_FBH + bs * 4352 + (kr * 136 + c * 8) * 2,
               Bh + (long)(k0 + kr) * D_ + n0 + c * 8);
          cp16(sb + O_FBL + bs * 4352 + (kr * 136 + c * 8) * 2,
               Bl + (long)(k0 + kr) * D_ + n0 + c * 8); }
        cp_commit();
    }

    for (int it = 0; it < NIT; it++) {
        const int as = it % 3, bs = it % 4, fs = it & 1;
        cp_wait<2>();
        __syncthreads();
        // convert + transpose A: staging [m][16] fp32 -> [k][136] fp16 h/l
#pragma unroll
        for (int p = 0; p < 4; p++) {
            int idx = t + p * 256;
            int m = idx & 127, kp = idx >> 7;     // kp 0..7
            float2 v = *(const float2*)(sm + O_STA + as * 8192 + (m * 16 + 2 * kp) * 4);
            __half hx = __float2half(v.x);
            __half lx = __float2half(v.x - __half2float(hx));
            __half hy = __float2half(v.y);
            __half ly = __float2half(v.y - __half2float(hy));
            __half* pH = (__half*)(sm + O_FAH + fs * 4352);
            __half* pL = (__half*)(sm + O_FAL + fs * 4352);
            pH[(2 * kp) * 136 + m] = hx;  pH[(2 * kp + 1) * 136 + m] = hy;
            pL[(2 * kp) * 136 + m] = lx;  pL[(2 * kp + 1) * 136 + m] = ly;
        }
        __syncthreads();
        if (it + 3 < NIT) {
            int k0 = (it + 3) * 16, as2 = (it + 3) % 3, bs2 = (it + 3) % 4;
#pragma unroll
            for (int r = 0; r < 2; r++) {
                int idx = t + r * 256, m = idx >> 2, c = idx & 3;
                cp16(sb + O_STA + as2 * 8192 + (m * 16 + c * 4) * 4,
                     Aq + (long)m * D_ + k0 + c * 4);
            }
            { int kr = t >> 4, c = t & 15;
              cp16(sb + O_FBH + bs2 * 4352 + (kr * 136 + c * 8) * 2,
                   Bh + (long)(k0 + kr) * D_ + n0 + c * 8);
              cp16(sb + O_FBL + bs2 * 4352 + (kr * 136 + c * 8) * 2,
                   Bl + (long)(k0 + kr) * D_ + n0 + c * 8); }
        }
        cp_commit();

        uint32_t aH[4][4], aL[4][4], bH[4][2], bL[4][2];
#pragma unroll
        for (int mt = 0; mt < 4; mt++) {
            int coff = wj * 64 + mt * 16;
            ldsm4t(frag_addr(sb + O_FAH + fs * 4352, lane, coff),
                   aH[mt][0], aH[mt][1], aH[mt][2], aH[mt][3]);
            ldsm4t(frag_addr(sb + O_FAL + fs * 4352, lane, coff),
                   aL[mt][0], aL[mt][1], aL[mt][2], aL[mt][3]);
        }
#pragma unroll
        for (int p = 0; p < 2; p++) {
            int coff = wl * 32 + p * 16;
            uint32_t r0, r1, r2, r3;
            ldsm4t(frag_addr(sb + O_FBH + bs * 4352, lane, coff), r0, r1, r2, r3);
            bH[2 * p][0] = r0; bH[2 * p][1] = r2;
            bH[2 * p + 1][0] = r1; bH[2 * p + 1][1] = r3;
            ldsm4t(frag_addr(sb + O_FBL + bs * 4352, lane, coff), r0, r1, r2, r3);
            bL[2 * p][0] = r0; bL[2 * p][1] = r2;
            bL[2 * p + 1][0] = r1; bL[2 * p + 1][1] = r3;
        }
#pragma unroll
        for (int mt = 0; mt < 4; mt++)
#pragma unroll
            for (int nt = 0; nt < 4; nt++) {
                mma16816(acc[mt][nt], aH[mt][0], aH[mt][1], aH[mt][2], aH[mt][3],
                         bH[nt][0], bH[nt][1]);
                mma16816(acc[mt][nt], aH[mt][0], aH[mt][1], aH[mt][2], aH[mt][3],
                         bL[nt][0], bL[nt][1]);
                mma16816(acc[mt][nt], aL[mt][0], aL[mt][1], aL[mt][2], aL[mt][3],
                         bH[nt][0], bH[nt][1]);
            }
    }

    const int g = lane >> 2, tig = lane & 3;
    const float* rb = g_r + b * D_;
    float* Ob = outp + ((long)b * N_ + m0) * D_;
#pragma unroll
    for (int mt = 0; mt < 4; mt++)
#pragma unroll
        for (int nt = 0; nt < 4; nt++) {
            int row = wj * 64 + mt * 16 + g;
            int col = n0 + wl * 32 + nt * 8 + 2 * tig;
            float2 o0, o1;
            o0.x = acc[mt][nt][0] + rb[col];
            o0.y = acc[mt][nt][1] + rb[col + 1];
            o1.x = acc[mt][nt][2] + rb[col];
            o1.y = acc[mt][nt][3] + rb[col + 1];
            *(float2*)(Ob + (long)row * D_ + col) = o0;
            *(float2*)(Ob + (long)(row + 8) * D_ + col) = o1;
        }
}

// ---------------- small SIMT GEMM (256x256) ----------------
template <int BM, int BN, int TM, int TN, int KSTEP, bool AKM, int EPI>
__global__ void __launch_bounds__((BM / TM) * (BN / TN)) gemm_tpl(
    const float* __restrict__ Ag, const float* __restrict__ Bg, float* __restrict__ Cg,
    long sAb, long sBb, long sCb,
    const float* __restrict__ bkv, const float* __restrict__ bvv, float scale)
{
    constexpr int TX = BN / TN;
    constexpr int TY = BM / TM;
    constexpr int NT = TX * TY;

    const int t  = threadIdx.x;
    const int tx = t % TX;
    const int ty = t / TX;
    const int b  = blockIdx.z;

    const float* A  = Ag + (long)b * sAb;
    const float* Bm = Bg + (long)b * sBb;
    float*       C  = Cg + (long)b * sCb;

    const int m0 = blockIdx.y * BM;
    const int n0 = blockIdx.x * BN;

    __shared__ float sA[AKM ? (KSTEP * BM) : (BM * (KSTEP + 1))];
    __shared__ float sB[KSTEP * BN];

    unsigned long long acc[TM][TN / 2];
#pragma unroll
    for (int i = 0; i < TM; i++)
#pragma unroll
        for (int j = 0; j < TN / 2; j++) acc[i][j] = 0ull;

    for (int k0 = 0; k0 < D_; k0 += KSTEP) {
        if constexpr (AKM) {
            constexpr int AF4 = KSTEP * BM / 4;
#pragma unroll
            for (int r = 0; r < AF4 / NT; r++) {
                int i  = t + r * NT;
                int kk = i / (BM / 4);
                int mq = i % (BM / 4);
                float4 v = *(const float4*)(A + (long)(k0 + kk) * D_ + m0 + mq * 4);
                *(float4*)(&sA[kk * BM + mq * 4]) = v;
            }
        } else {
            constexpr int AF4 = BM * (KSTEP / 4);
#pragma unroll
            for (int r = 0; r < AF4 / NT; r++) {
                int i  = t + r * NT;
                int mr = i / (KSTEP / 4);
                int kq = i % (KSTEP / 4);
                float4 v = *(const float4*)(A + (long)(m0 + mr) * D_ + k0 + kq * 4);
                int base = mr * (KSTEP + 1) + kq * 4;
                sA[base + 0] = v.x; sA[base + 1] = v.y;
                sA[base + 2] = v.z; sA[base + 3] = v.w;
            }
        }
        {
            constexpr int BF4 = KSTEP * BN / 4;
#pragma unroll
            for (int r = 0; r < BF4 / NT; r++) {
                int i  = t + r * NT;
                int kk = i / (BN / 4);
                int nq = i % (BN / 4);
                float4 v = *(const float4*)(Bm + (long)(k0 + kk) * D_ + n0 + nq * 4);
                *(float4*)(&sB[kk * BN + nq * 4]) = v;
            }
        }
        __syncthreads();

#pragma unroll 4
        for (int kk = 0; kk < KSTEP; kk++) {
            unsigned long long bb[TN / 2];
            const unsigned long long* bp =
                reinterpret_cast<const unsigned long long*>(&sB[kk * BN + tx * TN]);
#pragma unroll
            for (int j = 0; j < TN / 2; j++) bb[j] = bp[j];

            float av[TM];
            if constexpr (AKM) {
#pragma unroll
                for (int q = 0; q < TM / 4; q++) {
                    float4 va = *(const float4*)(&sA[kk * BM + ty * TM + q * 4]);
                    av[q * 4 + 0] = va.x; av[q * 4 + 1] = va.y;
                    av[q * 4 + 2] = va.z; av[q * 4 + 3] = va.w;
                }
            } else {
#pragma unroll
                for (int i = 0; i < TM; i++)
                    av[i] = sA[(ty * TM + i) * (KSTEP + 1) + kk];
            }
#pragma unroll
            for (int i = 0; i < TM; i++) {
                unsigned long long aa = pack2(av[i], av[i]);
#pragma unroll
                for (int j = 0; j < TN / 2; j++) ffma2(acc[i][j], aa, bb[j]);
            }
        }
        __syncthreads();
    }

#pragma unroll
    for (int i = 0; i < TM; i++) {
        int m = m0 + ty * TM + i;
        float vals[TN];
#pragma unroll
        for (int j = 0; j < TN / 2; j++) unpack2(acc[i][j], vals[2 * j], vals[2 * j + 1]);
        float* crow = C + (long)m * D_ + n0 + tx * TN;

        if constexpr (EPI == 2) {
            float um  = g_u[b * D_ + m];
            float bkm = bkv[m];
            float cb  = g_cnt[b];
#pragma unroll
            for (int j = 0; j < TN; j++) {
                int col = n0 + tx * TN + j;
                crow[j] = scale * (vals[j] + um * bvv[col] + bkm * g_w[b * D_ + col]
                                   + cb * bkm * bvv[col]);
            }
        } else {
#pragma unroll
            for (int q = 0; q < TN / 4; q++) {
                float4 o;
                o.x = vals[q * 4 + 0]; o.y = vals[q * 4 + 1];
                o.z = vals[q * 4 + 2]; o.w = vals[q * 4 + 3];
                *(float4*)(&crow[q * 4]) = o;
            }
        }
    }
}

// ---------------- small kernels ----------------
__global__ void k_zero() {
    int i = blockIdx.x * blockDim.x + threadIdx.x;
    if (i < B_ * D_ * D_) g_G[i] = 0.0f;
    if (i < B_ * D_) { g_sk[i] = 0.0f; g_sv[i] = 0.0f; }
    if (i < B_) g_cnt[i] = 0.0f;
    if (i == 0) { g_notint = 0; g_notfloat = 0; }
}

__global__ void k_flag(const float* __restrict__ bk, const float* __restrict__ bv) {
    __shared__ float red[D_];
    int t = threadIdx.x;
    red[t] = fabsf(bk[t]) + fabsf(bv[t]);
    __syncthreads();
    for (int s = 128; s > 0; s >>= 1) {
        if (t < s) red[t] += red[t + s];
        __syncthreads();
    }
    if (t == 0) g_biasflag = red[0];
}

__global__ void k_tr(const float* __restrict__ Wv) {
    g_WvT[blockIdx.x * D_ + threadIdx.x] = Wv[threadIdx.x * D_ + blockIdx.x];
}

__global__ void k_sums(const float* __restrict__ key, const float* __restrict__ val) {
    if (g_biasflag == 0.0f) return;
    int b = blockIdx.x;
    int d = threadIdx.x;
    float sk = 0.0f, sv = 0.0f, c = 0.0f;
    for (int n = 0; n < N_; n++) {
        float ml = g_mask8[(long)b * N_ + n] ? 0.0f : 1.0f;
        sk += ml * key[((long)b * N_ + n) * D_ + d];
        sv += ml * val[((long)b * N_ + n) * D_ + d];
        c  += ml;
    }
    g_sk[b * D_ + d] = sk;
    g_sv[b * D_ + d] = sv;
    if (d == 0) g_cnt[b] = c;
}

__global__ void k_uw(const float* __restrict__ Wk, const float* __restrict__ Wv) {
    int b = blockIdx.x;
    int d = threadIdx.x;
    float u = 0.0f, w = 0.0f;
    for (int j = 0; j < D_; j++) {
        u += Wk[d * D_ + j] * g_sk[b * D_ + j];
        w += g_sv[b * D_ + j] * Wv[d * D_ + j];
    }
    g_u[b * D_ + d] = u;
    g_w[b * D_ + d] = w;
}

__global__ void k_softmax() {
    int b = blockIdx.x;
    int e = threadIdx.x;
    float* p = g_S + (long)b * D_ * D_ + e;
    float mx = -1e30f;
    for (int d = 0; d < D_; d++) mx = fmaxf(mx, p[d * D_]);
    float s = 0.0f;
    for (int d = 0; d < D_; d++) {
        float v = expf(p[d * D_] - mx);
        s += v;
        p[d * D_] = v;
    }
    float inv = 1.0f / s;
    for (int d = 0; d < D_; d++) p[d * D_] *= inv;
}

__global__ void k_r(const float* __restrict__ bq) {
    int b = blockIdx.x;
    int e = threadIdx.x;
    float r = 0.0f;
    for (int d = 0; d < D_; d++) r += bq[d] * g_S[(long)b * D_ * D_ + d * D_ + e];
    g_r[b * D_ + e] = r;
}

__global__ void k_split() {
    int i = blockIdx.x * blockDim.x + threadIdx.x;   // [0, B*D*D)
    float x = g_C[i];
    __half h = __float2half(x);
    g_CTh[i] = h;
    g_CTl[i] = __float2half(x - __half2float(h));
}

// ---------------- launch ----------------
extern "C" void kernel_launch(void* const* d_in, const int* in_sizes, int n_in,
                              void* d_out, int out_size)
{
    const float* query = (const float*)d_in[0];
    const float* key   = (const float*)d_in[1];
    const float* value = (const float*)d_in[2];
    const void*  maskp = d_in[3];

    int wbase = 4;
    if (wbase < n_in && in_sizes[wbase] < 32) wbase++;   // skip need_weights scalar

    const float* Wq = (const float*)d_in[wbase + 0];
    const float* bq = (const float*)d_in[wbase + 1];
    const float* Wk = (const float*)d_in[wbase + 2];
    const float* bk = (const float*)d_in[wbase + 3];
    const float* Wv = (const float*)d_in[wbase + 4];
    const float* bv = (const float*)d_in[wbase + 5];
    float* out = (float*)d_out;

    float *pG, *pT, *pS, *pC, *pWvT;
    cudaGetSymbolAddress((void**)&pG, g_G);
    cudaGetSymbolAddress((void**)&pT, g_T);
    cudaGetSymbolAddress((void**)&pS, g_S);
    cudaGetSymbolAddress((void**)&pC, g_C);
    cudaGetSymbolAddress((void**)&pWvT, g_WvT);

    cudaFuncSetAttribute(gemm_gram_mma, cudaFuncAttributeMaxDynamicSharedMemorySize, G_SMEM);
    cudaFuncSetAttribute(gemm_out_mma,  cudaFuncAttributeMaxDynamicSharedMemorySize, O_SMEM);

    const float scale = 0.3535533905932738f;  // 1/sqrt(B)

    k_zero<<<(B_ * D_ * D_ + 255) / 256, 256>>>();            // 1
    k_maskdetect<<<16384 / 256, 256>>>(maskp);                // 2
    k_maskconv<<<(B_ * N_) / 256, 256>>>(maskp);              // 3
    k_flag<<<1, D_>>>(bk, bv);                                // 4
    k_tr<<<D_, D_>>>(Wv);                                     // 5

    // 6 (ncu slot): G via HMMA
    gemm_gram_mma<<<dim3(2, 2, B_ * GCH), 256, G_SMEM>>>(key, value);

    k_sums<<<B_, D_>>>(key, value);
    k_uw<<<B_, D_>>>(Wk, Wv);

    // T = Wk @ G
    gemm_tpl<64, 64, 4, 4, 32, false, 0>
        <<<dim3(4, 4, B_), 256>>>(Wk, pG, pT, 0L, (long)D_ * D_, (long)D_ * D_,
                                  nullptr, nullptr, 0.0f);
    // S = scale * (T @ WvT + bias terms)
    gemm_tpl<64, 64, 4, 4, 32, false, 2>
        <<<dim3(4, 4, B_), 256>>>(pT, pWvT, pS, (long)D_ * D_, 0L, (long)D_ * D_,
                                  bk, bv, scale);

    k_softmax<<<B_, D_>>>();
    k_r<<<B_, D_>>>(bq);

    // C[d][e] = sum_dd Wq[dd][d] * aw[dd][e]
    gemm_tpl<64, 64, 4, 4, 32, true, 0>
        <<<dim3(4, 4, B_), 256>>>(Wq, pS, pC, 0L, (long)D_ * D_, (long)D_ * D_,
                                  nullptr, nullptr, 0.0f);
    k_split<<<(B_ * D_ * D_) / 256, 256>>>();

    // out = query @ C + r via HMMA
    gemm_out_mma<<<dim3(2, 64, B_), 256, O_SMEM>>>(query, out);
}

// round 13
// speedup vs baseline: 2.9785x; 1.2590x over previous
#include <cuda_runtime.h>
#include <cuda_fp16.h>
#include <math.h>
#include <cstdint>

#define B_ 8
#define N_ 8192
#define D_ 256

// ---------------- device scratch ----------------
__device__ float g_WvT[D_ * D_];
__device__ float g_G[B_ * D_ * D_];
__device__ float g_T[B_ * D_ * D_];
__device__ float g_S[B_ * D_ * D_];
__device__ float g_C[B_ * D_ * D_];          // C[d][e]
__device__ float g_sk[B_ * D_];
__device__ float g_sv[B_ * D_];
__device__ float g_u[B_ * D_];
__device__ float g_w[B_ * D_];
__device__ float g_r[B_ * D_];
__device__ float g_cnt[B_];
__device__ float g_biasflag;                 // |bk|+|bv|
__device__ float g_biasflagq;                // |bq|
__device__ unsigned char g_mask8[B_ * N_];
__device__ int g_notint, g_notfloat;
__device__ __align__(16) __half g_CTh[B_ * D_ * D_];
__device__ __align__(16) __half g_CTl[B_ * D_ * D_];
// fp16 hi/lo split of key (masked) and value, natural [b][n][d] layout
__device__ __align__(16) __half g_Kh[(long)B_ * N_ * D_];
__device__ __align__(16) __half g_Kl[(long)B_ * N_ * D_];
__device__ __align__(16) __half g_Vh[(long)B_ * N_ * D_];
__device__ __align__(16) __half g_Vl[(long)B_ * N_ * D_];

// ---------------- f32x2 (small SIMT GEMMs) ----------------
__device__ __forceinline__ unsigned long long pack2(float x, float y) {
    unsigned long long r;
    asm("mov.b64 %0, {%1, %2};" : "=l"(r) : "f"(x), "f"(y));
    return r;
}
__device__ __forceinline__ void unpack2(unsigned long long v, float &x, float &y) {
    asm("mov.b64 {%0, %1}, %2;" : "=f"(x), "=f"(y) : "l"(v));
}
__device__ __forceinline__ void ffma2(unsigned long long &d, unsigned long long a,
                                      unsigned long long b) {
    asm("fma.rn.f32x2 %0, %1, %2, %0;" : "+l"(d) : "l"(a), "l"(b));
}

// ---------------- cp.async ----------------
__device__ __forceinline__ void cp16(uint32_t s, const void* g) {
    asm volatile("cp.async.ca.shared.global [%0], [%1], 16;\n" :: "r"(s), "l"(g));
}
__device__ __forceinline__ void cp_commit() { asm volatile("cp.async.commit_group;\n"); }
template <int NW>
__device__ __forceinline__ void cp_wait() {
    asm volatile("cp.async.wait_group %0;\n" :: "n"(NW));
}

// ---------------- mma.sync helpers ----------------
__device__ __forceinline__ void ldsm4t(uint32_t addr, uint32_t &r0, uint32_t &r1,
                                       uint32_t &r2, uint32_t &r3) {
    asm volatile("ldmatrix.sync.aligned.m8n8.x4.trans.shared.b16 {%0,%1,%2,%3}, [%4];"
                 : "=r"(r0), "=r"(r1), "=r"(r2), "=r"(r3) : "r"(addr));
}
__device__ __forceinline__ void mma16816(float* c, uint32_t a0, uint32_t a1,
                                         uint32_t a2, uint32_t a3,
                                         uint32_t b0, uint32_t b1) {
    asm volatile(
        "mma.sync.aligned.m16n8k16.row.col.f32.f16.f16.f32 "
        "{%0,%1,%2,%3}, {%4,%5,%6,%7}, {%8,%9}, {%0,%1,%2,%3};"
        : "+f"(c[0]), "+f"(c[1]), "+f"(c[2]), "+f"(c[3])
        : "r"(a0), "r"(a1), "r"(a2), "r"(a3), "r"(b0), "r"(b1));
}

// unified .trans fragment address: tile stored [k][136] halfs, k-major
__device__ __forceinline__ uint32_t frag_addr(uint32_t tile_base, int lane, int coff) {
    int lrow = (lane & 7) + ((lane & 16) >> 1);
    int lcol = coff + (lane & 8);
    return tile_base + (uint32_t)(lrow * 136 + lcol) * 2;
}

// ---------------- mask dtype detection ----------------
__global__ void k_maskdetect(const void* mp) {
    int i = blockIdx.x * blockDim.x + threadIdx.x;   // [0, 16384)
    int v = ((const int*)mp)[i];
    if (v != 0 && v != 1) atomicOr(&g_notint, 1);
    float f = ((const float*)mp)[i];
    if (!(f == 0.0f || f == 1.0f)) atomicOr(&g_notfloat, 1);
}
__global__ void k_maskconv(const void* mp) {
    int i = blockIdx.x * blockDim.x + threadIdx.x;   // [0, B*N)
    unsigned char m;
    if (!g_notint)        m = (((const int*)mp)[i] != 0);
    else if (!g_notfloat) m = (((const float*)mp)[i] != 0.0f);
    else                  m = (((const unsigned char*)mp)[i] != 0);
    g_mask8[i] = m;
}

// ---------------- presplit: key/value -> fp16 hi/lo, mask folded into key ----------------
__global__ void k_presplit(const float* __restrict__ key, const float* __restrict__ val,
                           const void* __restrict__ mp) {
    long i = (long)blockIdx.x * blockDim.x + threadIdx.x;   // [0, B*N*D/4)
    long e0 = i * 4;
    int bn = (int)(e0 >> 8);   // D_=256
    bool m;
    if (!g_notint)        m = (((const int*)mp)[bn] != 0);
    else if (!g_notfloat) m = (((const float*)mp)[bn] != 0.0f);
    else                  m = (((const unsigned char*)mp)[bn] != 0);

    float4 kv = *(const float4*)(key + e0);
    if (m) { kv.x = 0.0f; kv.y = 0.0f; kv.z = 0.0f; kv.w = 0.0f; }
    {
        __half2 h0 = __floats2half2_rn(kv.x, kv.y);
        __half2 h1 = __floats2half2_rn(kv.z, kv.w);
        float2 f0 = __half22float2(h0), f1 = __half22float2(h1);
        __half2 l0 = __floats2half2_rn(kv.x - f0.x, kv.y - f0.y);
        __half2 l1 = __floats2half2_rn(kv.z - f1.x, kv.w - f1.y);
        uint2 ph; ph.x = *(uint32_t*)&h0; ph.y = *(uint32_t*)&h1;
        uint2 pl; pl.x = *(uint32_t*)&l0; pl.y = *(uint32_t*)&l1;
        *(uint2*)(g_Kh + e0) = ph;
        *(uint2*)(g_Kl + e0) = pl;
    }
    float4 vv = *(const float4*)(val + e0);
    {
        __half2 h0 = __floats2half2_rn(vv.x, vv.y);
        __half2 h1 = __floats2half2_rn(vv.z, vv.w);
        float2 f0 = __half22float2(h0), f1 = __half22float2(h1);
        __half2 l0 = __floats2half2_rn(vv.x - f0.x, vv.y - f0.y);
        __half2 l1 = __floats2half2_rn(vv.z - f1.x, vv.w - f1.y);
        uint2 ph; ph.x = *(uint32_t*)&h0; ph.y = *(uint32_t*)&h1;
        uint2 pl; pl.x = *(uint32_t*)&l0; pl.y = *(uint32_t*)&l1;
        *(uint2*)(g_Vh + e0) = ph;
        *(uint2*)(g_Vl + e0) = pl;
    }
}

// ================= G = K^T V via HMMA on presplit fp16 =================
// CTA: 128(j) x 128(l), 8 warps (warp 64x32), KS=32, 2-stage cp.async.
#define GCH 8
#define G_TILE 8704                 // 32 * 136 * 2 bytes
#define G_STG  (4 * G_TILE)         // Ah, Al, Bh, Bl
#define G_SMEM (2 * G_STG)          // 69632

__global__ void __launch_bounds__(256) gemm_gram_mma()
{
    extern __shared__ __align__(16) char sm[];
    const uint32_t sb = (uint32_t)__cvta_generic_to_shared(sm);
    const int t = threadIdx.x, lane = t & 31, w = t >> 5;
    const int wj = w & 1, wl = w >> 1;
    const int n0 = blockIdx.x * 128, m0 = blockIdx.y * 128;
    const int b = blockIdx.z >> 3, ch = blockIdx.z & 7;
    const int kbeg = ch * (N_ / GCH);
    const int NIT = (N_ / GCH) / 32;     // 32

    // static per-thread cp mapping: 8 reps
    const __half* srcp[8];
    uint32_t dstp[8];
#pragma unroll
    for (int r = 0; r < 8; r++) {
        int idx = t + r * 256;
        int tile = idx >> 9, j = idx & 511, kr = j >> 4, c = j & 15;
        const __half* base = (tile == 0) ? g_Kh : (tile == 1) ? g_Kl
                           : (tile == 2) ? g_Vh : g_Vl;
        int col0 = (tile < 2) ? m0 : n0;
        srcp[r] = base + ((long)b * N_ + kbeg + kr) * D_ + col0 + c * 8;
        dstp[r] = sb + tile * G_TILE + (uint32_t)(kr * 272 + c * 16);
    }

    float acc[4][4][4];
#pragma unroll
    for (int i = 0; i < 4; i++)
#pragma unroll
        for (int j = 0; j < 4; j++)
#pragma unroll
            for (int q = 0; q < 4; q++) acc[i][j][q] = 0.0f;

    // prologue: stage 0
#pragma unroll
    for (int r = 0; r < 8; r++) cp16(dstp[r], srcp[r]);
    cp_commit();

    for (int it = 0; it < NIT; it++) {
        const int s = it & 1;
        if (it + 1 < NIT) {
            long koff = (long)(it + 1) * 32 * D_;
            uint32_t soff = ((it + 1) & 1) * G_STG;
#pragma unroll
            for (int r = 0; r < 8; r++) cp16(dstp[r] + soff, srcp[r] + koff);
            cp_commit();
            cp_wait<1>();
        } else {
            cp_wait<0>();
        }
        __syncthreads();

#pragma unroll
        for (int h = 0; h < 2; h++) {
            const uint32_t tb = sb + s * G_STG + h * 4352;
            uint32_t aH[4][4], aL[4][4], bH[4][2], bL[4][2];
#pragma unroll
            for (int mt = 0; mt < 4; mt++) {
                int coff = wj * 64 + mt * 16;
                ldsm4t(frag_addr(tb, lane, coff),
                       aH[mt][0], aH[mt][1], aH[mt][2], aH[mt][3]);
                ldsm4t(frag_addr(tb + G_TILE, lane, coff),
                       aL[mt][0], aL[mt][1], aL[mt][2], aL[mt][3]);
            }
#pragma unroll
            for (int p = 0; p < 2; p++) {
                int coff = wl * 32 + p * 16;
                uint32_t r0, r1, r2, r3;
                ldsm4t(frag_addr(tb + 2 * G_TILE, lane, coff), r0, r1, r2, r3);
                bH[2 * p][0] = r0; bH[2 * p][1] = r2;
                bH[2 * p + 1][0] = r1; bH[2 * p + 1][1] = r3;
                ldsm4t(frag_addr(tb + 3 * G_TILE, lane, coff), r0, r1, r2, r3);
                bL[2 * p][0] = r0; bL[2 * p][1] = r2;
                bL[2 * p + 1][0] = r1; bL[2 * p + 1][1] = r3;
            }
#pragma unroll
            for (int mt = 0; mt < 4; mt++)
#pragma unroll
                for (int nt = 0; nt < 4; nt++) {
                    mma16816(acc[mt][nt], aH[mt][0], aH[mt][1], aH[mt][2], aH[mt][3],
                             bH[nt][0], bH[nt][1]);
                    mma16816(acc[mt][nt], aH[mt][0], aH[mt][1], aH[mt][2], aH[mt][3],
                             bL[nt][0], bL[nt][1]);
                    mma16816(acc[mt][nt], aL[mt][0], aL[mt][1], aL[mt][2], aL[mt][3],
                             bH[nt][0], bH[nt][1]);
                }
        }
        __syncthreads();
    }

    // epilogue: atomic accumulate into g_G
    const int g = lane >> 2, tig = lane & 3;
    float* Cb = g_G + (long)b * D_ * D_;
#pragma unroll
    for (int mt = 0; mt < 4; mt++)
#pragma unroll
        for (int nt = 0; nt < 4; nt++) {
            int row = m0 + wj * 64 + mt * 16 + g;
            int col = n0 + wl * 32 + nt * 8 + 2 * tig;
            float* cr = Cb + (long)row * D_ + col;
            atomicAdd(cr,              acc[mt][nt][0]);
            atomicAdd(cr + 1,          acc[mt][nt][1]);
            atomicAdd(cr + 8 * D_,     acc[mt][nt][2]);
            atomicAdd(cr + 8 * D_ + 1, acc[mt][nt][3]);
        }
}

// ================= out = query @ C + r via HMMA, fp16 split =================
#define O_STA 0                      // fp32 staging A: 3 x 8192
#define O_FAH 24576                  // fp16 A hi: 2 x 4352
#define O_FAL 33280
#define O_FBH 41984                  // fp16 B hi: 4 x 4352
#define O_FBL 59392
#define O_SMEM 76800

__global__ void __launch_bounds__(256) gemm_out_mma(
    const float* __restrict__ query, float* __restrict__ outp)
{
    extern __shared__ __align__(16) char sm[];
    const uint32_t sb = (uint32_t)__cvta_generic_to_shared(sm);
    const int t = threadIdx.x, lane = t & 31, w = t >> 5;
    const int wj = w & 1, wl = w >> 1;
    const int n0 = blockIdx.x * 128, m0 = blockIdx.y * 128;
    const int b = blockIdx.z;
    const int NIT = D_ / 16;   // 16

    const float* Aq = query + ((long)b * N_ + m0) * D_;
    const __half* Bh = g_CTh + (long)b * D_ * D_;
    const __half* Bl = g_CTl + (long)b * D_ * D_;

    float acc[4][4][4];
#pragma unroll
    for (int i = 0; i < 4; i++)
#pragma unroll
        for (int j = 0; j < 4; j++)
#pragma unroll
            for (int q = 0; q < 4; q++) acc[i][j][q] = 0.0f;

#pragma unroll
    for (int j = 0; j < 3; j++) {
        int k0 = j * 16, as = j % 3, bs = j % 4;
#pragma unroll
        for (int r = 0; r < 2; r++) {
            int idx = t + r * 256, m = idx >> 2, c = idx & 3;
            cp16(sb + O_STA + as * 8192 + (m * 16 + c * 4) * 4,
                 Aq + (long)m * D_ + k0 + c * 4);
        }
        { int kr = t >> 4, c = t & 15;
          cp16(sb + O_FBH + bs * 4352 + (kr * 136 + c * 8) * 2,
               Bh + (long)(k0 + kr) * D_ + n0 + c * 8);
          cp16(sb + O_FBL + bs * 4352 + (kr * 136 + c * 8) * 2,
               Bl + (long)(k0 + kr) * D_ + n0 + c * 8); }
        cp_commit();
    }

    for (int it = 0; it < NIT; it++) {
        const int as = it % 3, bs = it % 4, fs = it & 1;
        cp_wait<2>();
        __syncthreads();
#pragma unroll
        for (int p = 0; p < 4; p++) {
            int idx = t + p * 256;
            int m = idx & 127, kp = idx >> 7;     // kp 0..7
            float2 v = *(const float2*)(sm + O_STA + as * 8192 + (m * 16 + 2 * kp) * 4);
            __half hx = __float2half(v.x);
            __half lx = __float2half(v.x - __half2float(hx));
            __half hy = __float2half(v.y);
            __half ly = __float2half(v.y - __half2float(hy));
            __half* pH = (__half*)(sm + O_FAH + fs * 4352);
            __half* pL = (__half*)(sm + O_FAL + fs * 4352);
            pH[(2 * kp) * 136 + m] = hx;  pH[(2 * kp + 1) * 136 + m] = hy;
            pL[(2 * kp) * 136 + m] = lx;  pL[(2 * kp + 1) * 136 + m] = ly;
        }
        __syncthreads();
        if (it + 3 < NIT) {
            int k0 = (it + 3) * 16, as2 = (it + 3) % 3, bs2 = (it + 3) % 4;
#pragma unroll
            for (int r = 0; r < 2; r++) {
                int idx = t + r * 256, m = idx >> 2, c = idx & 3;
                cp16(sb + O_STA + as2 * 8192 + (m * 16 + c * 4) * 4,
                     Aq + (long)m * D_ + k0 + c * 4);
            }
            { int kr = t >> 4, c = t & 15;
              cp16(sb + O_FBH + bs2 * 4352 + (kr * 136 + c * 8) * 2,
                   Bh + (long)(k0 + kr) * D_ + n0 + c * 8);
              cp16(sb + O_FBL + bs2 * 4352 + (kr * 136 + c * 8) * 2,
                   Bl + (long)(k0 + kr) * D_ + n0 + c * 8); }
        }
        cp_commit();

        uint32_t aH[4][4], aL[4][4], bH[4][2], bL[4][2];
#pragma unroll
        for (int mt = 0; mt < 4; mt++) {
            int coff = wj * 64 + mt * 16;
            ldsm4t(frag_addr(sb + O_FAH + fs * 4352, lane, coff),
                   aH[mt][0], aH[mt][1], aH[mt][2], aH[mt][3]);
            ldsm4t(frag_addr(sb + O_FAL + fs * 4352, lane, coff),
                   aL[mt][0], aL[mt][1], aL[mt][2], aL[mt][3]);
        }
#pragma unroll
        for (int p = 0; p < 2; p++) {
            int coff = wl * 32 + p * 16;
            uint32_t r0, r1, r2, r3;
            ldsm4t(frag_addr(sb + O_FBH + bs * 4352, lane, coff), r0, r1, r2, r3);
            bH[2 * p][0] = r0; bH[2 * p][1] = r2;
            bH[2 * p + 1][0] = r1; bH[2 * p + 1][1] = r3;
            ldsm4t(frag_addr(sb + O_FBL + bs * 4352, lane, coff), r0, r1, r2, r3);
            bL[2 * p][0] = r0; bL[2 * p][1] = r2;
            bL[2 * p + 1][0] = r1; bL[2 * p + 1][1] = r3;
        }
#pragma unroll
        for (int mt = 0; mt < 4; mt++)
#pragma unroll
            for (int nt = 0; nt < 4; nt++) {
                mma16816(acc[mt][nt], aH[mt][0], aH[mt][1], aH[mt][2], aH[mt][3],
                         bH[nt][0], bH[nt][1]);
                mma16816(acc[mt][nt], aH[mt][0], aH[mt][1], aH[mt][2], aH[mt][3],
                         bL[nt][0], bL[nt][1]);
                mma16816(acc[mt][nt], aL[mt][0], aL[mt][1], aL[mt][2], aL[mt][3],
                         bH[nt][0], bH[nt][1]);
            }
    }

    const int g = lane >> 2, tig = lane & 3;
    const float* rb = g_r + b * D_;
    float* Ob = outp + ((long)b * N_ + m0) * D_;
#pragma unroll
    for (int mt = 0; mt < 4; mt++)
#pragma unroll
        for (int nt = 0; nt < 4; nt++) {
            int row = wj * 64 + mt * 16 + g;
            int col = n0 + wl * 32 + nt * 8 + 2 * tig;
            float2 o0, o1;
            o0.x = acc[mt][nt][0] + rb[col];
            o0.y = acc[mt][nt][1] + rb[col + 1];
            o1.x = acc[mt][nt][2] + rb[col];
            o1.y = acc[mt][nt][3] + rb[col + 1];
            *(float2*)(Ob + (long)row * D_ + col) = o0;
            *(float2*)(Ob + (long)(row + 8) * D_ + col) = o1;
        }
}

// ---------------- small SIMT GEMM (256x256) ----------------
template <int BM, int BN, int TM, int TN, int KSTEP, bool AKM, int EPI>
__global__ void __launch_bounds__((BM / TM) * (BN / TN)) gemm_tpl(
    const float* __restrict__ Ag, const float* __restrict__ Bg, float* __restrict__ Cg,
    long sAb, long sBb, long sCb,
    const float* __restrict__ bkv, const float* __restrict__ bvv, float scale)
{
    constexpr int TX = BN / TN;
    constexpr int TY = BM / TM;
    constexpr int NT = TX * TY;

    const int t  = threadIdx.x;
    const int tx = t % TX;
    const int ty = t / TX;
    const int b  = blockIdx.z;

    const float* A  = Ag + (long)b * sAb;
    const float* Bm = Bg + (long)b * sBb;
    float*       C  = Cg + (long)b * sCb;

    const int m0 = blockIdx.y * BM;
    const int n0 = blockIdx.x * BN;

    __shared__ float sA[AKM ? (KSTEP * BM) : (BM * (KSTEP + 1))];
    __shared__ float sB[KSTEP * BN];

    unsigned long long acc[TM][TN / 2];
#pragma unroll
    for (int i = 0; i < TM; i++)
#pragma unroll
        for (int j = 0; j < TN / 2; j++) acc[i][j] = 0ull;

    for (int k0 = 0; k0 < D_; k0 += KSTEP) {
        if constexpr (AKM) {
            constexpr int AF4 = KSTEP * BM / 4;
#pragma unroll
            for (int r = 0; r < AF4 / NT; r++) {
                int i  = t + r * NT;
                int kk = i / (BM / 4);
                int mq = i % (BM / 4);
                float4 v = *(const float4*)(A + (long)(k0 + kk) * D_ + m0 + mq * 4);
                *(float4*)(&sA[kk * BM + mq * 4]) = v;
            }
        } else {
            constexpr int AF4 = BM * (KSTEP / 4);
#pragma unroll
            for (int r = 0; r < AF4 / NT; r++) {
                int i  = t + r * NT;
                int mr = i / (KSTEP / 4);
                int kq = i % (KSTEP / 4);
                float4 v = *(const float4*)(A + (long)(m0 + mr) * D_ + k0 + kq * 4);
                int base = mr * (KSTEP + 1) + kq * 4;
                sA[base + 0] = v.x; sA[base + 1] = v.y;
                sA[base + 2] = v.z; sA[base + 3] = v.w;
            }
        }
        {
            constexpr int BF4 = KSTEP * BN / 4;
#pragma unroll
            for (int r = 0; r < BF4 / NT; r++) {
                int i  = t + r * NT;
                int kk = i / (BN / 4);
                int nq = i % (BN / 4);
                float4 v = *(const float4*)(Bm + (long)(k0 + kk) * D_ + n0 + nq * 4);
                *(float4*)(&sB[kk * BN + nq * 4]) = v;
            }
        }
        __syncthreads();

#pragma unroll 4
        for (int kk = 0; kk < KSTEP; kk++) {
            unsigned long long bb[TN / 2];
            const unsigned long long* bp =
                reinterpret_cast<const unsigned long long*>(&sB[kk * BN + tx * TN]);
#pragma unroll
            for (int j = 0; j < TN / 2; j++) bb[j] = bp[j];

            float av[TM];
            if constexpr (AKM) {
#pragma unroll
                for (int q = 0; q < TM / 4; q++) {
                    float4 va = *(const float4*)(&sA[kk * BM + ty * TM + q * 4]);
                    av[q * 4 + 0] = va.x; av[q * 4 + 1] = va.y;
                    av[q * 4 + 2] = va.z; av[q * 4 + 3] = va.w;
                }
            } else {
#pragma unroll
                for (int i = 0; i < TM; i++)
                    av[i] = sA[(ty * TM + i) * (KSTEP + 1) + kk];
            }
#pragma unroll
            for (int i = 0; i < TM; i++) {
                unsigned long long aa = pack2(av[i], av[i]);
#pragma unroll
                for (int j = 0; j < TN / 2; j++) ffma2(acc[i][j], aa, bb[j]);
            }
        }
        __syncthreads();
    }

#pragma unroll
    for (int i = 0; i < TM; i++) {
        int m = m0 + ty * TM + i;
        float vals[TN];
#pragma unroll
        for (int j = 0; j < TN / 2; j++) unpack2(acc[i][j], vals[2 * j], vals[2 * j + 1]);
        float* crow = C + (long)m * D_ + n0 + tx * TN;

        if constexpr (EPI == 2) {
            float um  = g_u[b * D_ + m];
            float bkm = bkv[m];
            float cb  = g_cnt[b];
#pragma unroll
            for (int j = 0; j < TN; j++) {
                int col = n0 + tx * TN + j;
                crow[j] = scale * (vals[j] + um * bvv[col] + bkm * g_w[b * D_ + col]
                                   + cb * bkm * bvv[col]);
            }
        } else {
#pragma unroll
            for (int q = 0; q < TN / 4; q++) {
                float4 o;
                o.x = vals[q * 4 + 0]; o.y = vals[q * 4 + 1];
                o.z = vals[q * 4 + 2]; o.w = vals[q * 4 + 3];
                *(float4*)(&crow[q * 4]) = o;
            }
        }
    }
}

// ---------------- small kernels ----------------
__global__ void k_zero() {
    int i = blockIdx.x * blockDim.x + threadIdx.x;
    if (i < B_ * D_ * D_) g_G[i] = 0.0f;
    if (i < B_ * D_) { g_sk[i] = 0.0f; g_sv[i] = 0.0f; g_r[i] = 0.0f; }
    if (i < B_) g_cnt[i] = 0.0f;
    if (i == 0) { g_notint = 0; g_notfloat = 0; }
}

__global__ void k_flag(const float* __restrict__ bk, const float* __restrict__ bv,
                       const float* __restrict__ bq) {
    __shared__ float red[D_], redq[D_];
    int t = threadIdx.x;
    red[t]  = fabsf(bk[t]) + fabsf(bv[t]);
    redq[t] = fabsf(bq[t]);
    __syncthreads();
    for (int s = 128; s > 0; s >>= 1) {
        if (t < s) { red[t] += red[t + s]; redq[t] += redq[t + s]; }
        __syncthreads();
    }
    if (t == 0) { g_biasflag = red[0]; g_biasflagq = redq[0]; }
}

__global__ void k_tr(const float* __restrict__ Wv) {
    g_WvT[blockIdx.x * D_ + threadIdx.x] = Wv[threadIdx.x * D_ + blockIdx.x];
}

__global__ void k_sums(const float* __restrict__ key, const float* __restrict__ val) {
    if (g_biasflag == 0.0f) return;
    int b = blockIdx.x;
    int d = threadIdx.x;
    float sk = 0.0f, sv = 0.0f, c = 0.0f;
    for (int n = 0; n < N_; n++) {
        float ml = g_mask8[(long)b * N_ + n] ? 0.0f : 1.0f;
        sk += ml * key[((long)b * N_ + n) * D_ + d];
        sv += ml * val[((long)b * N_ + n) * D_ + d];
        c  += ml;
    }
    g_sk[b * D_ + d] = sk;
    g_sv[b * D_ + d] = sv;
    if (d == 0) g_cnt[b] = c;
}

__global__ void k_uw(const float* __restrict__ Wk, const float* __restrict__ Wv) {
    if (g_biasflag == 0.0f) {
        g_u[blockIdx.x * D_ + threadIdx.x] = 0.0f;
        g_w[blockIdx.x * D_ + threadIdx.x] = 0.0f;
        return;
    }
    int b = blockIdx.x;
    int d = threadIdx.x;
    float u = 0.0f, w = 0.0f;
    for (int j = 0; j < D_; j++) {
        u += Wk[d * D_ + j] * g_sk[b * D_ + j];
        w += g_sv[b * D_ + j] * Wv[d * D_ + j];
    }
    g_u[b * D_ + d] = u;
    g_w[b * D_ + d] = w;
}

// coalesced softmax over d: grid (B, 8), block 256; warp w covers d-range,
// lanes cover 32 consecutive e-columns.
__global__ void k_softmax() {
    __shared__ float pm[8][33], cmv[32], ps[8][33], csv[32];
    int b = blockIdx.x, eg = blockIdx.y;
    int lane = threadIdx.x & 31, w = threadIdx.x >> 5;
    float* S = g_S + (long)b * D_ * D_ + eg * 32;

    float mx = -1e30f;
#pragma unroll 4
    for (int dd = 0; dd < 32; dd++)
        mx = fmaxf(mx, S[(w * 32 + dd) * D_ + lane]);
    pm[w][lane] = mx;
    __syncthreads();
    if (w == 0) {
        float m2 = -1e30f;
#pragma unroll
        for (int q = 0; q < 8; q++) m2 = fmaxf(m2, pm[q][lane]);
        cmv[lane] = m2;
    }
    __syncthreads();
    float cmx = cmv[lane];
    float sum = 0.0f;
#pragma unroll 4
    for (int dd = 0; dd < 32; dd++) {
        float v = expf(S[(w * 32 + dd) * D_ + lane] - cmx);
        S[(w * 32 + dd) * D_ + lane] = v;
        sum += v;
    }
    ps[w][lane] = sum;
    __syncthreads();
    if (w == 0) {
        float s2 = 0.0f;
#pragma unroll
        for (int q = 0; q < 8; q++) s2 += ps[q][lane];
        csv[lane] = 1.0f / s2;
    }
    __syncthreads();
    float inv = csv[lane];
#pragma unroll 4
    for (int dd = 0; dd < 32; dd++)
        S[(w * 32 + dd) * D_ + lane] *= inv;
}

__global__ void k_r(const float* __restrict__ bq) {
    if (g_biasflagq == 0.0f) return;    // g_r already zeroed
    int b = blockIdx.x;
    int e = threadIdx.x;
    float r = 0.0f;
    for (int d = 0; d < D_; d++) r += bq[d] * g_S[(long)b * D_ * D_ + d * D_ + e];
    g_r[b * D_ + e] = r;
}

__global__ void k_split() {
    int i = blockIdx.x * blockDim.x + threadIdx.x;   // [0, B*D*D)
    float x = g_C[i];
    __half h = __float2half(x);
    g_CTh[i] = h;
    g_CTl[i] = __float2half(x - __half2float(h));
}

// ---------------- launch ----------------
extern "C" void kernel_launch(void* const* d_in, const int* in_sizes, int n_in,
                              void* d_out, int out_size)
{
    const float* query = (const float*)d_in[0];
    const float* key   = (const float*)d_in[1];
    const float* value = (const float*)d_in[2];
    const void*  maskp = d_in[3];

    int wbase = 4;
    if (wbase < n_in && in_sizes[wbase] < 32) wbase++;   // skip need_weights scalar

    const float* Wq = (const float*)d_in[wbase + 0];
    const float* bq = (const float*)d_in[wbase + 1];
    const float* Wk = (const float*)d_in[wbase + 2];
    const float* bk = (const float*)d_in[wbase + 3];
    const float* Wv = (const float*)d_in[wbase + 4];
    const float* bv = (const float*)d_in[wbase + 5];
    float* out = (float*)d_out;

    float *pG, *pT, *pS, *pC, *pWvT;
    cudaGetSymbolAddress((void**)&pG, g_G);
    cudaGetSymbolAddress((void**)&pT, g_T);
    cudaGetSymbolAddress((void**)&pS, g_S);
    cudaGetSymbolAddress((void**)&pC, g_C);
    cudaGetSymbolAddress((void**)&pWvT, g_WvT);

    cudaFuncSetAttribute(gemm_gram_mma, cudaFuncAttributeMaxDynamicSharedMemorySize, G_SMEM);
    cudaFuncSetAttribute(gemm_out_mma,  cudaFuncAttributeMaxDynamicSharedMemorySize, O_SMEM);

    const float scale = 0.3535533905932738f;  // 1/sqrt(B)

    k_zero<<<(B_ * D_ * D_ + 255) / 256, 256>>>();                       // 1
    k_maskdetect<<<16384 / 256, 256>>>(maskp);                           // 2
    k_presplit<<<(int)((long)B_ * N_ * D_ / 4 / 256), 256>>>(key, value, maskp); // 3

    // 4 (ncu slot): G via HMMA on presplit fp16
    gemm_gram_mma<<<dim3(2, 2, B_ * GCH), 256, G_SMEM>>>();

    k_maskconv<<<(B_ * N_) / 256, 256>>>(maskp);                         // 5 (bias path)
    k_flag<<<1, D_>>>(bk, bv, bq);                                       // 6
    k_tr<<<D_, D_>>>(Wv);                                                // 7
    k_sums<<<B_, D_>>>(key, value);                                      // 8
    k_uw<<<B_, D_>>>(Wk, Wv);                                            // 9

    // T = Wk @ G
    gemm_tpl<64, 64, 4, 4, 32, false, 0>
        <<<dim3(4, 4, B_), 256>>>(Wk, pG, pT, 0L, (long)D_ * D_, (long)D_ * D_,
                                  nullptr, nullptr, 0.0f);
    // S = scale * (T @ WvT + bias terms)
    gemm_tpl<64, 64, 4, 4, 32, false, 2>
        <<<dim3(4, 4, B_), 256>>>(pT, pWvT, pS, (long)D_ * D_, 0L, (long)D_ * D_,
                                  bk, bv, scale);

    k_softmax<<<dim3(B_, 8), 256>>>();
    k_r<<<B_, D_>>>(bq);

    // C[d][e] = sum_dd Wq[dd][d] * aw[dd][e]
    gemm_tpl<64, 64, 4, 4, 32, true, 0>
        <<<dim3(4, 4, B_), 256>>>(Wq, pS, pC, 0L, (long)D_ * D_, (long)D_ * D_,
                                  nullptr, nullptr, 0.0f);
    k_split<<<(B_ * D_ * D_) / 256, 256>>>();

    // out = query @ C + r via HMMA
    gemm_out_mma<<<dim3(2, 64, B_), 256, O_SMEM>>>(query, out);
}